// round 2
// baseline (speedup 1.0000x reference)
#include <cuda_runtime.h>
#include <math.h>

// ---------------- constants ----------------
#define DM    512          // D_MODEL
#define LQ    1024         // SEQ
#define LK    1024         // MEMLEN
#define NB    4            // BATCH
#define NH    8            // heads
#define HD    64           // head dim
#define DI    1024         // D_INNER
#define DS    16           // D_STATE
#define DTR   32           // DT_RANK
#define ROWS  (NB*LQ)      // 4096

// ---------------- scratch (static device, no allocs) ----------------
__device__ float g_q   [ROWS*DM];
__device__ float g_k   [ROWS*DM];
__device__ float g_v   [ROWS*DM];
__device__ float g_sc  [(long)NB*NH*LQ*LK];   // 128 MB scores
__device__ float g_ao  [ROWS*DM];
__device__ float g_x1  [ROWS*DM];
__device__ float g_xz  [ROWS*2*DI];
__device__ float g_u   [ROWS*DI];
__device__ float g_xdbl[ROWS*(DTR+2*DS)];
__device__ float g_dt  [ROWS*DI];
__device__ float g_y   [ROWS*DI];
__device__ float g_ym  [ROWS*DI];
__device__ float g_m   [ROWS*DM];
__device__ float g_x2  [ROWS*DM];
__device__ float g_fh  [ROWS*4*DM];
__device__ float g_ff  [ROWS*DM];

// ---------------- GEMM: C = alpha * A @ op(B) (+bias)(+act) ----------------
// A: M x K row-major (lda). TRANSB: B stored [N][K] (ldb over K). else [K][N].
// Batched via blockIdx.z: off = (z/zdiv)*s?o + (z%zdiv)*s?i
#define BM 128
#define BN 64
#define BKK 16
#define TM 8
#define TN 4

enum { EPI_NONE = 0, EPI_BIAS = 1, EPI_SOFTPLUS = 2, EPI_GELU = 3 };

template <bool TRANSB, int EPI>
__global__ __launch_bounds__(256) void gemm_kernel(
    const float* __restrict__ A, int lda, long sAo, long sAi,
    const float* __restrict__ B, int ldb, long sBo, long sBi,
    float* __restrict__ C, int ldc, long sCo, long sCi,
    int M, int N, int K, int zdiv,
    const float* __restrict__ bias, float alpha)
{
    int z = blockIdx.z;
    int zo = z / zdiv, zi = z % zdiv;
    A += zo * sAo + zi * sAi;
    B += zo * sBo + zi * sBi;
    C += zo * sCo + zi * sCi;

    __shared__ float As[BKK][BM + 1];
    __shared__ float Bs[BKK][BN + 1];

    int tid = threadIdx.x;
    int tx = tid % (BN / TN);   // 0..15
    int ty = tid / (BN / TN);   // 0..15
    int row0 = blockIdx.y * BM;
    int col0 = blockIdx.x * BN;

    float acc[TM][TN];
#pragma unroll
    for (int i = 0; i < TM; i++)
#pragma unroll
        for (int j = 0; j < TN; j++) acc[i][j] = 0.f;

    int a_col = tid % BKK;   // 0..15
    int a_row = tid / BKK;   // 0..15

    for (int k0 = 0; k0 < K; k0 += BKK) {
#pragma unroll
        for (int r = 0; r < 8; r++) {
            int m = a_row + 16 * r;
            As[a_col][m] = A[(long)(row0 + m) * lda + k0 + a_col];
        }
        if (TRANSB) {
#pragma unroll
            for (int r = 0; r < 4; r++) {
                int n = a_row + 16 * r;
                Bs[a_col][n] = B[(long)(col0 + n) * ldb + k0 + a_col];
            }
        } else {
            int bn = tid % BN, bk = tid / BN;   // bk 0..3
#pragma unroll
            for (int r = 0; r < 4; r++) {
                int kk = bk + 4 * r;
                Bs[kk][bn] = B[(long)(k0 + kk) * ldb + col0 + bn];
            }
        }
        __syncthreads();
#pragma unroll
        for (int kk = 0; kk < BKK; kk++) {
            float a[TM], b[TN];
#pragma unroll
            for (int i = 0; i < TM; i++) a[i] = As[kk][ty * TM + i];
#pragma unroll
            for (int j = 0; j < TN; j++) b[j] = Bs[kk][tx * TN + j];
#pragma unroll
            for (int i = 0; i < TM; i++)
#pragma unroll
                for (int j = 0; j < TN; j++) acc[i][j] = fmaf(a[i], b[j], acc[i][j]);
        }
        __syncthreads();
    }

#pragma unroll
    for (int i = 0; i < TM; i++) {
        int m = row0 + ty * TM + i;
#pragma unroll
        for (int j = 0; j < TN; j++) {
            int n = col0 + tx * TN + j;
            float val = acc[i][j] * alpha;
            if (EPI >= 1) val += bias[n];
            if (EPI == EPI_SOFTPLUS) val = (val > 20.f) ? val : log1pf(expf(val));
            if (EPI == EPI_GELU)     val = 0.5f * val * (1.f + erff(val * 0.70710678118f));
            C[(long)m * ldc + n] = val;
        }
    }
}

// ---------------- softmax over rows of length 1024 ----------------
__global__ __launch_bounds__(256) void softmax_kernel(float* __restrict__ S)
{
    long row = blockIdx.x;
    float* p = S + row * (long)LK;
    int tid = threadIdx.x;
    __shared__ float sred[8];

    float v[4];
    float mx = -1e30f;
#pragma unroll
    for (int i = 0; i < 4; i++) { v[i] = p[tid + 256 * i]; mx = fmaxf(mx, v[i]); }
#pragma unroll
    for (int o = 16; o; o >>= 1) mx = fmaxf(mx, __shfl_xor_sync(0xffffffffu, mx, o));
    if ((tid & 31) == 0) sred[tid >> 5] = mx;
    __syncthreads();
    if (tid < 8) {
        float t = sred[tid];
#pragma unroll
        for (int o = 4; o; o >>= 1) t = fmaxf(t, __shfl_xor_sync(0xffu, t, o));
        sred[tid] = t;
    }
    __syncthreads();
    mx = sred[0];
    __syncthreads();

    float sum = 0.f;
#pragma unroll
    for (int i = 0; i < 4; i++) { v[i] = __expf(v[i] - mx); sum += v[i]; }
#pragma unroll
    for (int o = 16; o; o >>= 1) sum += __shfl_xor_sync(0xffffffffu, sum, o);
    if ((tid & 31) == 0) sred[tid >> 5] = sum;
    __syncthreads();
    if (tid < 8) {
        float t = sred[tid];
#pragma unroll
        for (int o = 4; o; o >>= 1) t += __shfl_xor_sync(0xffu, t, o);
        sred[tid] = t;
    }
    __syncthreads();
    float inv = 1.f / sred[0];
#pragma unroll
    for (int i = 0; i < 4; i++) p[tid + 256 * i] = v[i] * inv;
}

// ---------------- add + layernorm over rows of 512 ----------------
__global__ __launch_bounds__(256) void addln_kernel(
    const float* __restrict__ X, const float* __restrict__ R,
    const float* __restrict__ gg, const float* __restrict__ bb,
    float* __restrict__ O)
{
    long row = blockIdx.x;
    const float* x = X + row * DM;
    const float* r = R + row * DM;
    int tid = threadIdx.x;
    __shared__ float s1[8], s2[8];

    float v0 = x[tid] + r[tid];
    float v1 = x[tid + 256] + r[tid + 256];
    float s = v0 + v1;
    float ss = v0 * v0 + v1 * v1;
#pragma unroll
    for (int o = 16; o; o >>= 1) {
        s += __shfl_xor_sync(0xffffffffu, s, o);
        ss += __shfl_xor_sync(0xffffffffu, ss, o);
    }
    if ((tid & 31) == 0) { s1[tid >> 5] = s; s2[tid >> 5] = ss; }
    __syncthreads();
    if (tid < 8) {
        float a = s1[tid], c = s2[tid];
#pragma unroll
        for (int o = 4; o; o >>= 1) {
            a += __shfl_xor_sync(0xffu, a, o);
            c += __shfl_xor_sync(0xffu, c, o);
        }
        s1[tid] = a; s2[tid] = c;
    }
    __syncthreads();
    float mu  = s1[0] * (1.f / DM);
    float var = s2[0] * (1.f / DM) - mu * mu;
    float inv = rsqrtf(var + 1e-5f);
    O[row * DM + tid]       = (v0 - mu) * inv * gg[tid]       + bb[tid];
    O[row * DM + tid + 256] = (v1 - mu) * inv * gg[tid + 256] + bb[tid + 256];
}

// ---------------- depthwise causal conv(4) + SiLU ----------------
__global__ __launch_bounds__(256) void conv_silu_kernel(
    const float* __restrict__ xz, const float* __restrict__ cw,
    const float* __restrict__ cb, float* __restrict__ u)
{
    long idx = (long)blockIdx.x * 256 + threadIdx.x;   // over ROWS*DI
    int d = (int)(idx % DI);
    long bt = idx / DI;
    int t = (int)(bt % LQ);
    long b = bt / LQ;
    const float* base = xz + (b * LQ) * (long)(2 * DI) + d;   // xm[b][.][d], stride 2*DI
    float acc = cb[d];
#pragma unroll
    for (int j = 0; j < 4; j++) {
        int tt = t + j - 3;
        if (tt >= 0) acc = fmaf(base[(long)tt * (2 * DI)], cw[d * 4 + j], acc);
    }
    u[idx] = acc / (1.f + expf(-acc));
}

// ---------------- selective scan ----------------
// grid: (DI/16, NB). block 256 = 8 warps; warp = 2 channels x 16 states.
__global__ __launch_bounds__(256) void scan_kernel(
    const float* __restrict__ xdbl,   // (ROWS, 64): B at +32, C at +48
    const float* __restrict__ dt,     // (ROWS, DI)
    const float* __restrict__ u,      // (ROWS, DI)
    const float* __restrict__ A_log,  // (DI, DS)
    float* __restrict__ y)            // (ROWS, DI)
{
    int b = blockIdx.y;
    int ch0 = blockIdx.x * 16;
    int tid = threadIdx.x;
    int warp = tid >> 5, lane = tid & 31;
    int half = lane >> 4, s = lane & 15;
    int ch_local = warp * 2 + half;
    int ch = ch0 + ch_local;

    __shared__ float Bsh[64][DS];
    __shared__ float Csh[64][DS];
    __shared__ float dsh[16][65];
    __shared__ float ush[16][65];

    float Ac = -expf(A_log[ch * DS + s]);
    float h = 0.f;

    const float* xb  = xdbl + (long)b * LQ * 64;
    const float* dtb = dt   + (long)b * LQ * DI;
    const float* ub  = u    + (long)b * LQ * DI;
    float*       yb  = y    + (long)b * LQ * DI;

    for (int t0 = 0; t0 < LQ; t0 += 64) {
        __syncthreads();
#pragma unroll
        for (int r = 0; r < 4; r++) {
            int i = tid + 256 * r;            // 0..1023
            int tl = i >> 4, sl = i & 15;
            Bsh[tl][sl] = xb[(long)(t0 + tl) * 64 + DTR + sl];
            Csh[tl][sl] = xb[(long)(t0 + tl) * 64 + DTR + DS + sl];
            dsh[sl][tl] = dtb[(long)(t0 + tl) * DI + ch0 + sl];
            ush[sl][tl] = ub [(long)(t0 + tl) * DI + ch0 + sl];
        }
        __syncthreads();
#pragma unroll 4
        for (int tl = 0; tl < 64; tl++) {
            float dtv = dsh[ch_local][tl];
            float dA = __expf(dtv * Ac);
            h = fmaf(h, dA, dtv * Bsh[tl][s] * ush[ch_local][tl]);
            float p = h * Csh[tl][s];
            p += __shfl_xor_sync(0xffffffffu, p, 1);
            p += __shfl_xor_sync(0xffffffffu, p, 2);
            p += __shfl_xor_sync(0xffffffffu, p, 4);
            p += __shfl_xor_sync(0xffffffffu, p, 8);
            if (s == 0) yb[(long)(t0 + tl) * DI + ch] = p;
        }
    }
}

// ---------------- gate: ym = (y + u*Dp) * silu(z) ----------------
__global__ __launch_bounds__(256) void gate_kernel(
    const float* __restrict__ y, const float* __restrict__ u,
    const float* __restrict__ Dp, const float* __restrict__ xz,
    float* __restrict__ out)
{
    long idx = (long)blockIdx.x * 256 + threadIdx.x;   // over ROWS*DI
    int d = (int)(idx % DI);
    long bt = idx / DI;
    float z = xz[bt * (2 * DI) + DI + d];
    float val = (y[idx] + u[idx] * Dp[d]) * (z / (1.f + expf(-z)));
    out[idx] = val;
}

// ---------------- launcher ----------------
static float* sym(const void* s)
{
    void* p = nullptr;
    cudaGetSymbolAddress(&p, s);
    return (float*)p;
}

extern "C" void kernel_launch(void* const* d_in, const int* in_sizes, int n_in,
                              void* d_out, int out_size)
{
    const float* x      = (const float*)d_in[0];
    const float* memory = (const float*)d_in[1];
    const float* Wq = (const float*)d_in[2];  const float* bq = (const float*)d_in[3];
    const float* Wk = (const float*)d_in[4];  const float* bk = (const float*)d_in[5];
    const float* Wv = (const float*)d_in[6];  const float* bv = (const float*)d_in[7];
    const float* Wo = (const float*)d_in[8];  const float* bo = (const float*)d_in[9];
    const float* ln1g = (const float*)d_in[10]; const float* ln1b = (const float*)d_in[11];
    const float* ln2g = (const float*)d_in[12]; const float* ln2b = (const float*)d_in[13];
    const float* ln3g = (const float*)d_in[14]; const float* ln3b = (const float*)d_in[15];
    const float* W_in   = (const float*)d_in[16];
    const float* conv_w = (const float*)d_in[17];
    const float* conv_b = (const float*)d_in[18];
    const float* W_xproj = (const float*)d_in[19];
    const float* W_dt    = (const float*)d_in[20];
    const float* b_dt    = (const float*)d_in[21];
    const float* A_log   = (const float*)d_in[22];
    const float* D_p     = (const float*)d_in[23];
    const float* W_out   = (const float*)d_in[24];
    const float* W1 = (const float*)d_in[25]; const float* b1 = (const float*)d_in[26];
    const float* W2 = (const float*)d_in[27]; const float* b2 = (const float*)d_in[28];
    float* out = (float*)d_out;

    float* q    = sym(g_q);    float* k    = sym(g_k);    float* v   = sym(g_v);
    float* sc   = sym(g_sc);   float* ao   = sym(g_ao);   float* x1  = sym(g_x1);
    float* xz   = sym(g_xz);   float* u    = sym(g_u);    float* xd  = sym(g_xdbl);
    float* dtb  = sym(g_dt);   float* y    = sym(g_y);    float* ym  = sym(g_ym);
    float* m    = sym(g_m);    float* x2   = sym(g_x2);   float* fh  = sym(g_fh);
    float* ff   = sym(g_ff);

#define GEMM(TB, EPI, A, lda, sAo, sAi, B, ldb, sBo, sBi, C, ldc, sCo, sCi, M, N, K, Z, zdiv, bias, alpha) \
    gemm_kernel<TB, EPI><<<dim3((N)/BN, (M)/BM, (Z)), 256>>>(                                              \
        A, lda, sAo, sAi, B, ldb, sBo, sBi, C, ldc, sCo, sCi, M, N, K, zdiv, bias, alpha)

    // --- cross attention ---
    GEMM(true, EPI_BIAS, x,      DM, 0L, 0L, Wq, DM, 0L, 0L, q, DM, 0L, 0L, ROWS, DM, DM, 1, 1, bq, 1.f);
    GEMM(true, EPI_BIAS, memory, DM, 0L, 0L, Wk, DM, 0L, 0L, k, DM, 0L, 0L, ROWS, DM, DM, 1, 1, bk, 1.f);
    GEMM(true, EPI_BIAS, memory, DM, 0L, 0L, Wv, DM, 0L, 0L, v, DM, 0L, 0L, ROWS, DM, DM, 1, 1, bv, 1.f);

    // scores[b,h] = (1/8) * q_bh @ k_bh^T   (z = b*8+h)
    GEMM(true, EPI_NONE,
         q, DM, (long)LQ * DM, (long)HD,
         k, DM, (long)LK * DM, (long)HD,
         sc, LK, (long)NH * LQ * LK, (long)LQ * LK,
         LQ, LK, HD, NB * NH, NH, (const float*)nullptr, 0.125f);

    softmax_kernel<<<NB * NH * LQ, 256>>>(sc);

    // out_bh = attn_bh @ v_bh     (B not transposed)
    GEMM(false, EPI_NONE,
         sc, LK, (long)NH * LQ * LK, (long)LQ * LK,
         v, DM, (long)LK * DM, (long)HD,
         ao, DM, (long)LQ * DM, (long)HD,
         LQ, HD, LK, NB * NH, NH, (const float*)nullptr, 1.f);

    // o-proj (reuse q buffer as output)
    GEMM(true, EPI_BIAS, ao, DM, 0L, 0L, Wo, DM, 0L, 0L, q, DM, 0L, 0L, ROWS, DM, DM, 1, 1, bo, 1.f);

    addln_kernel<<<ROWS, 256>>>(x, q, ln1g, ln1b, x1);

    // --- mamba ---
    GEMM(true, EPI_NONE, x1, DM, 0L, 0L, W_in, DM, 0L, 0L, xz, 2 * DI, 0L, 0L, ROWS, 2 * DI, DM, 1, 1, (const float*)nullptr, 1.f);

    conv_silu_kernel<<<(ROWS * DI) / 256, 256>>>(xz, conv_w, conv_b, u);

    GEMM(true, EPI_NONE, u, DI, 0L, 0L, W_xproj, DI, 0L, 0L, xd, DTR + 2 * DS, 0L, 0L, ROWS, DTR + 2 * DS, DI, 1, 1, (const float*)nullptr, 1.f);

    // dt = softplus(dt_r @ W_dt^T + b_dt); dt_r is first 32 cols of xdbl (lda=64)
    GEMM(true, EPI_SOFTPLUS, xd, DTR + 2 * DS, 0L, 0L, W_dt, DTR, 0L, 0L, dtb, DI, 0L, 0L, ROWS, DI, DTR, 1, 1, b_dt, 1.f);

    scan_kernel<<<dim3(DI / 16, NB), 256>>>(xd, dtb, u, A_log, y);

    gate_kernel<<<(ROWS * DI) / 256, 256>>>(y, u, D_p, xz, ym);

    GEMM(true, EPI_NONE, ym, DI, 0L, 0L, W_out, DI, 0L, 0L, m, DM, 0L, 0L, ROWS, DM, DI, 1, 1, (const float*)nullptr, 1.f);

    addln_kernel<<<ROWS, 256>>>(x1, m, ln2g, ln2b, x2);

    // --- FFN ---
    GEMM(true, EPI_GELU, x2, DM, 0L, 0L, W1, DM, 0L, 0L, fh, 4 * DM, 0L, 0L, ROWS, 4 * DM, DM, 1, 1, b1, 1.f);
    GEMM(true, EPI_BIAS, fh, 4 * DM, 0L, 0L, W2, 4 * DM, 0L, 0L, ff, DM, 0L, 0L, ROWS, DM, 4 * DM, 1, 1, b2, 1.f);

    addln_kernel<<<ROWS, 256>>>(x2, ff, ln3g, ln3b, out);

#undef GEMM
}

// round 5
// speedup vs baseline: 1.5029x; 1.5029x over previous
#include <cuda_runtime.h>
#include <mma.h>
#include <math.h>
#include <type_traits>

using namespace nvcuda;

// ---------------- constants ----------------
#define DM    512          // D_MODEL
#define LQ    1024         // SEQ
#define LK    1024         // MEMLEN
#define NB    4            // BATCH
#define NH    8            // heads
#define HD    64           // head dim
#define DI    1024         // D_INNER
#define DS    16           // D_STATE
#define DTR   32           // DT_RANK
#define ROWS  (NB*LQ)      // 4096

// ---------------- scratch (static device, no allocs) ----------------
__device__ float g_q   [ROWS*DM];
__device__ float g_k   [ROWS*DM];
__device__ float g_v   [ROWS*DM];
__device__ float g_sc  [(long)NB*NH*LQ*LK];   // 128 MB scores
__device__ float g_ao  [ROWS*DM];
__device__ float g_x1  [ROWS*DM];
__device__ float g_xz  [ROWS*2*DI];
__device__ float g_u   [ROWS*DI];
__device__ float g_xdbl[ROWS*(DTR+2*DS)];
__device__ float g_dt  [ROWS*DI];
__device__ float g_y   [ROWS*DI];
__device__ float g_ym  [ROWS*DI];
__device__ float g_m   [ROWS*DM];
__device__ float g_x2  [ROWS*DM];
__device__ float g_fh  [ROWS*4*DM];
__device__ float g_ff  [ROWS*DM];

enum { EPI_NONE = 0, EPI_BIAS = 1, EPI_SOFTPLUS = 2, EPI_GELU = 3 };

// ---------------- TF32 wmma GEMM ----------------
// C = alpha * A @ op(B) (+bias)(+act)
// A: M x K row-major (lda). TRANSB: B stored [N][K]; else [K][N].
// Batched via blockIdx.z: off = (z/zdiv)*s?o + (z%zdiv)*s?i
// Tiles: BM x BN, 8 warps arranged WR x WC. Warp tile (BM/WR) x (BN/WC).
// Requires: K % 16 == 0, lda/ldb/ldc % 4 == 0, WTN == 32.

template <int BM, int BN, int WR, int WC, bool TRANSB, int EPI>
__global__ __launch_bounds__(256, 2) void tgemm(
    const float* __restrict__ A, int lda, long sAo, long sAi,
    const float* __restrict__ B, int ldb, long sBo, long sBi,
    float* __restrict__ C, int ldc, long sCo, long sCi,
    int K, int zdiv,
    const float* __restrict__ bias, float alpha)
{
    constexpr int BK   = 16;
    constexpr int WTM  = BM / WR;            // warp tile M
    constexpr int WTN  = BN / WC;            // warp tile N (always 32 here)
    constexpr int FM   = WTM / 16;
    constexpr int FN   = WTN / 16;
    constexpr int LDAS = BK + 4;             // 20 floats (80B, 16B-multiple)
    constexpr int LDBS = BK + 4;             // for TRANSB layout [BN][LDBS]
    constexpr int LDBN = BN + 4;             // for !TRANSB layout [BK][LDBN]
    constexpr int ASZ  = BM * LDAS;
    constexpr int BSZ  = TRANSB ? BN * LDBS : BK * LDBN;
    constexpr int ESLB = 16 * (WTN + 4);     // per-warp epilogue slab
    constexpr int SMEMF = (ASZ + BSZ) > (8 * ESLB) ? (ASZ + BSZ) : (8 * ESLB);

    __shared__ float smem[SMEMF];
    float* As = smem;
    float* Bs = smem + ASZ;

    int z = blockIdx.z;
    int zo = z / zdiv, zi = z % zdiv;
    A += zo * sAo + zi * sAi;
    B += zo * sBo + zi * sBi;
    C += zo * sCo + zi * sCi;

    const int tid  = threadIdx.x;
    const int wid  = tid >> 5;
    const int lane = tid & 31;
    const int warp_m = wid / WC;
    const int warp_n = wid % WC;
    const int row0 = blockIdx.y * BM;
    const int col0 = blockIdx.x * BN;

    using BLayout = typename std::conditional<TRANSB, wmma::col_major, wmma::row_major>::type;

    wmma::fragment<wmma::accumulator, 16, 16, 8, float> acc[FM][FN];
#pragma unroll
    for (int i = 0; i < FM; i++)
#pragma unroll
        for (int j = 0; j < FN; j++) wmma::fill_fragment(acc[i][j], 0.f);

    for (int k0 = 0; k0 < K; k0 += BK) {
        // ---- load A tile: BM x BK (float4 per thread) ----
        constexpr int AITER = (BM * BK) / (256 * 4);
#pragma unroll
        for (int r = 0; r < AITER; r++) {
            int t = tid + 256 * r;
            int m  = t >> 2;             // BK/4 = 4 slots per row
            int kc = (t & 3) * 4;
            float4 val = *(const float4*)&A[(long)(row0 + m) * lda + k0 + kc];
            *(float4*)&As[m * LDAS + kc] = val;
        }
        // ---- load B tile ----
        if (TRANSB) {
            constexpr int BITER = (BN * BK) / (256 * 4) ? (BN * BK) / (256 * 4) : 1;
#pragma unroll
            for (int r = 0; r < BITER; r++) {
                int t = tid + 256 * r;
                int n  = t >> 2;
                int kc = (t & 3) * 4;
                float4 val = *(const float4*)&B[(long)(col0 + n) * ldb + k0 + kc];
                *(float4*)&Bs[n * LDBS + kc] = val;
            }
        } else {
            constexpr int NV = BN / 4;                   // float4 per row
            constexpr int BITER = (BK * NV) / 256 ? (BK * NV) / 256 : 1;
#pragma unroll
            for (int r = 0; r < BITER; r++) {
                int t = tid + 256 * r;
                int k  = t / NV;
                int nc = (t % NV) * 4;
                float4 val = *(const float4*)&B[(long)(k0 + k) * ldb + col0 + nc];
                *(float4*)&Bs[k * LDBN + nc] = val;
            }
        }
        __syncthreads();

        // ---- two k-steps of 8 ----
#pragma unroll
        for (int kk = 0; kk < BK; kk += 8) {
            wmma::fragment<wmma::matrix_a, 16, 16, 8, wmma::precision::tf32, wmma::row_major> af[FM];
#pragma unroll
            for (int i = 0; i < FM; i++) {
                wmma::load_matrix_sync(af[i], &As[(warp_m * WTM + i * 16) * LDAS + kk], LDAS);
#pragma unroll
                for (int t = 0; t < af[i].num_elements; t++)
                    af[i].x[t] = wmma::__float_to_tf32(af[i].x[t]);
            }
            wmma::fragment<wmma::matrix_b, 16, 16, 8, wmma::precision::tf32, BLayout> bf[FN];
#pragma unroll
            for (int j = 0; j < FN; j++) {
                const float* bptr = TRANSB ? &Bs[(warp_n * WTN + j * 16) * LDBS + kk]
                                           : &Bs[kk * LDBN + warp_n * WTN + j * 16];
                const int bld = TRANSB ? LDBS : LDBN;
                wmma::load_matrix_sync(bf[j], bptr, bld);
#pragma unroll
                for (int t = 0; t < bf[j].num_elements; t++)
                    bf[j].x[t] = wmma::__float_to_tf32(bf[j].x[t]);
            }
#pragma unroll
            for (int i = 0; i < FM; i++)
#pragma unroll
                for (int j = 0; j < FN; j++)
                    wmma::mma_sync(acc[i][j], af[i], bf[j], acc[i][j]);
        }
        __syncthreads();
    }

    // ---- epilogue via per-warp smem slab (16 x WTN) ----
    float* slab = smem + wid * ESLB;
#pragma unroll
    for (int i = 0; i < FM; i++) {
#pragma unroll
        for (int j = 0; j < FN; j++)
            wmma::store_matrix_sync(slab + j * 16, acc[i][j], WTN + 4, wmma::mem_row_major);
        __syncwarp();
        int c = lane;                                  // WTN == 32
        int n = col0 + warp_n * WTN + c;
        float bv = (EPI >= 1) ? bias[n] : 0.f;
#pragma unroll
        for (int r = 0; r < 16; r++) {
            float val = slab[r * (WTN + 4) + c] * alpha + bv;
            if (EPI == EPI_SOFTPLUS) val = (val > 20.f) ? val : log1pf(expf(val));
            if (EPI == EPI_GELU)     val = 0.5f * val * (1.f + erff(val * 0.70710678118f));
            C[(long)(row0 + warp_m * WTM + i * 16 + r) * ldc + n] = val;
        }
        __syncwarp();
    }
}

// ---------------- softmax over rows of length 1024 ----------------
__global__ __launch_bounds__(256) void softmax_kernel(float* __restrict__ S)
{
    long row = blockIdx.x;
    float* p = S + row * (long)LK;
    int tid = threadIdx.x;
    __shared__ float sred[8];

    float v[4];
    float mx = -1e30f;
#pragma unroll
    for (int i = 0; i < 4; i++) { v[i] = p[tid + 256 * i]; mx = fmaxf(mx, v[i]); }
#pragma unroll
    for (int o = 16; o; o >>= 1) mx = fmaxf(mx, __shfl_xor_sync(0xffffffffu, mx, o));
    if ((tid & 31) == 0) sred[tid >> 5] = mx;
    __syncthreads();
    if (tid < 8) {
        float t = sred[tid];
#pragma unroll
        for (int o = 4; o; o >>= 1) t = fmaxf(t, __shfl_xor_sync(0xffu, t, o));
        sred[tid] = t;
    }
    __syncthreads();
    mx = sred[0];
    __syncthreads();

    float sum = 0.f;
#pragma unroll
    for (int i = 0; i < 4; i++) { v[i] = __expf(v[i] - mx); sum += v[i]; }
#pragma unroll
    for (int o = 16; o; o >>= 1) sum += __shfl_xor_sync(0xffffffffu, sum, o);
    if ((tid & 31) == 0) sred[tid >> 5] = sum;
    __syncthreads();
    if (tid < 8) {
        float t = sred[tid];
#pragma unroll
        for (int o = 4; o; o >>= 1) t += __shfl_xor_sync(0xffu, t, o);
        sred[tid] = t;
    }
    __syncthreads();
    float inv = 1.f / sred[0];
#pragma unroll
    for (int i = 0; i < 4; i++) p[tid + 256 * i] = v[i] * inv;
}

// ---------------- add + layernorm over rows of 512 ----------------
__global__ __launch_bounds__(256) void addln_kernel(
    const float* __restrict__ X, const float* __restrict__ R,
    const float* __restrict__ gg, const float* __restrict__ bb,
    float* __restrict__ O)
{
    long row = blockIdx.x;
    const float* x = X + row * DM;
    const float* r = R + row * DM;
    int tid = threadIdx.x;
    __shared__ float s1[8], s2[8];

    float v0 = x[tid] + r[tid];
    float v1 = x[tid + 256] + r[tid + 256];
    float s = v0 + v1;
    float ss = v0 * v0 + v1 * v1;
#pragma unroll
    for (int o = 16; o; o >>= 1) {
        s += __shfl_xor_sync(0xffffffffu, s, o);
        ss += __shfl_xor_sync(0xffffffffu, ss, o);
    }
    if ((tid & 31) == 0) { s1[tid >> 5] = s; s2[tid >> 5] = ss; }
    __syncthreads();
    if (tid < 8) {
        float a = s1[tid], c = s2[tid];
#pragma unroll
        for (int o = 4; o; o >>= 1) {
            a += __shfl_xor_sync(0xffu, a, o);
            c += __shfl_xor_sync(0xffu, c, o);
        }
        s1[tid] = a; s2[tid] = c;
    }
    __syncthreads();
    float mu  = s1[0] * (1.f / DM);
    float var = s2[0] * (1.f / DM) - mu * mu;
    float inv = rsqrtf(var + 1e-5f);
    O[row * DM + tid]       = (v0 - mu) * inv * gg[tid]       + bb[tid];
    O[row * DM + tid + 256] = (v1 - mu) * inv * gg[tid + 256] + bb[tid + 256];
}

// ---------------- depthwise causal conv(4) + SiLU ----------------
__global__ __launch_bounds__(256) void conv_silu_kernel(
    const float* __restrict__ xz, const float* __restrict__ cw,
    const float* __restrict__ cb, float* __restrict__ u)
{
    long idx = (long)blockIdx.x * 256 + threadIdx.x;   // over ROWS*DI
    int d = (int)(idx % DI);
    long bt = idx / DI;
    int t = (int)(bt % LQ);
    long b = bt / LQ;
    const float* base = xz + (b * LQ) * (long)(2 * DI) + d;   // xm[b][.][d], stride 2*DI
    float acc = cb[d];
#pragma unroll
    for (int j = 0; j < 4; j++) {
        int tt = t + j - 3;
        if (tt >= 0) acc = fmaf(base[(long)tt * (2 * DI)], cw[d * 4 + j], acc);
    }
    u[idx] = acc / (1.f + expf(-acc));
}

// ---------------- selective scan ----------------
__global__ __launch_bounds__(256) void scan_kernel(
    const float* __restrict__ xdbl,   // (ROWS, 64): B at +32, C at +48
    const float* __restrict__ dt,     // (ROWS, DI)
    const float* __restrict__ u,      // (ROWS, DI)
    const float* __restrict__ A_log,  // (DI, DS)
    float* __restrict__ y)            // (ROWS, DI)
{
    int b = blockIdx.y;
    int ch0 = blockIdx.x * 16;
    int tid = threadIdx.x;
    int warp = tid >> 5, lane = tid & 31;
    int half = lane >> 4, s = lane & 15;
    int ch_local = warp * 2 + half;
    int ch = ch0 + ch_local;

    __shared__ float Bsh[64][DS];
    __shared__ float Csh[64][DS];
    __shared__ float dsh[16][65];
    __shared__ float ush[16][65];

    float Ac = -expf(A_log[ch * DS + s]);
    float h = 0.f;

    const float* xb  = xdbl + (long)b * LQ * 64;
    const float* dtb = dt   + (long)b * LQ * DI;
    const float* ub  = u    + (long)b * LQ * DI;
    float*       yb  = y    + (long)b * LQ * DI;

    for (int t0 = 0; t0 < LQ; t0 += 64) {
        __syncthreads();
#pragma unroll
        for (int r = 0; r < 4; r++) {
            int i = tid + 256 * r;            // 0..1023
            int tl = i >> 4, sl = i & 15;
            Bsh[tl][sl] = xb[(long)(t0 + tl) * 64 + DTR + sl];
            Csh[tl][sl] = xb[(long)(t0 + tl) * 64 + DTR + DS + sl];
            dsh[sl][tl] = dtb[(long)(t0 + tl) * DI + ch0 + sl];
            ush[sl][tl] = ub [(long)(t0 + tl) * DI + ch0 + sl];
        }
        __syncthreads();
#pragma unroll 4
        for (int tl = 0; tl < 64; tl++) {
            float dtv = dsh[ch_local][tl];
            float dA = __expf(dtv * Ac);
            h = fmaf(h, dA, dtv * Bsh[tl][s] * ush[ch_local][tl]);
            float p = h * Csh[tl][s];
            p += __shfl_xor_sync(0xffffffffu, p, 1);
            p += __shfl_xor_sync(0xffffffffu, p, 2);
            p += __shfl_xor_sync(0xffffffffu, p, 4);
            p += __shfl_xor_sync(0xffffffffu, p, 8);
            if (s == 0) yb[(long)(t0 + tl) * DI + ch] = p;
        }
    }
}

// ---------------- gate: ym = (y + u*Dp) * silu(z) ----------------
__global__ __launch_bounds__(256) void gate_kernel(
    const float* __restrict__ y, const float* __restrict__ u,
    const float* __restrict__ Dp, const float* __restrict__ xz,
    float* __restrict__ out)
{
    long idx = (long)blockIdx.x * 256 + threadIdx.x;   // over ROWS*DI
    int d = (int)(idx % DI);
    long bt = idx / DI;
    float z = xz[bt * (2 * DI) + DI + d];
    float val = (y[idx] + u[idx] * Dp[d]) * (z / (1.f + expf(-z)));
    out[idx] = val;
}

// ---------------- launcher ----------------
static float* sym(const void* s)
{
    void* p = nullptr;
    cudaGetSymbolAddress(&p, s);
    return (float*)p;
}

extern "C" void kernel_launch(void* const* d_in, const int* in_sizes, int n_in,
                              void* d_out, int out_size)
{
    const float* x      = (const float*)d_in[0];
    const float* memory = (const float*)d_in[1];
    const float* Wq = (const float*)d_in[2];  const float* bq = (const float*)d_in[3];
    const float* Wk = (const float*)d_in[4];  const float* bk = (const float*)d_in[5];
    const float* Wv = (const float*)d_in[6];  const float* bv = (const float*)d_in[7];
    const float* Wo = (const float*)d_in[8];  const float* bo = (const float*)d_in[9];
    const float* ln1g = (const float*)d_in[10]; const float* ln1b = (const float*)d_in[11];
    const float* ln2g = (const float*)d_in[12]; const float* ln2b = (const float*)d_in[13];
    const float* ln3g = (const float*)d_in[14]; const float* ln3b = (const float*)d_in[15];
    const float* W_in   = (const float*)d_in[16];
    const float* conv_w = (const float*)d_in[17];
    const float* conv_b = (const float*)d_in[18];
    const float* W_xproj = (const float*)d_in[19];
    const float* W_dt    = (const float*)d_in[20];
    const float* b_dt    = (const float*)d_in[21];
    const float* A_log   = (const float*)d_in[22];
    const float* D_p     = (const float*)d_in[23];
    const float* W_out   = (const float*)d_in[24];
    const float* W1 = (const float*)d_in[25]; const float* b1 = (const float*)d_in[26];
    const float* W2 = (const float*)d_in[27]; const float* b2 = (const float*)d_in[28];
    float* out = (float*)d_out;

    float* q    = sym(g_q);    float* k    = sym(g_k);    float* v   = sym(g_v);
    float* sc   = sym(g_sc);   float* ao   = sym(g_ao);   float* x1  = sym(g_x1);
    float* xz   = sym(g_xz);   float* u    = sym(g_u);    float* xd  = sym(g_xdbl);
    float* dtb  = sym(g_dt);   float* y    = sym(g_y);    float* ym  = sym(g_ym);
    float* m    = sym(g_m);    float* x2   = sym(g_x2);   float* fh  = sym(g_fh);
    float* ff   = sym(g_ff);

    // big-N config: 128x128 tile, warps 2x4 (warp tile 64x32)
#define TG_BIG(TB, EPI, A, lda, sAo, sAi, B, ldb, sBo, sBi, C, ldc, sCo, sCi, M, N, K, Z, zdiv, bias, alpha) \
    tgemm<128, 128, 2, 4, TB, EPI><<<dim3((N)/128, (M)/128, (Z)), 256>>>(                                    \
        A, lda, sAo, sAi, B, ldb, sBo, sBi, C, ldc, sCo, sCi, K, zdiv, bias, alpha)
    // N=64 config: 128x64 tile, warps 4x2 (warp tile 32x32)
#define TG_N64(TB, EPI, A, lda, sAo, sAi, B, ldb, sBo, sBi, C, ldc, sCo, sCi, M, N, K, Z, zdiv, bias, alpha) \
    tgemm<128, 64, 4, 2, TB, EPI><<<dim3((N)/64, (M)/128, (Z)), 256>>>(                                      \
        A, lda, sAo, sAi, B, ldb, sBo, sBi, C, ldc, sCo, sCi, K, zdiv, bias, alpha)

    // --- cross attention ---
    TG_BIG(true, EPI_BIAS, x,      DM, 0L, 0L, Wq, DM, 0L, 0L, q, DM, 0L, 0L, ROWS, DM, DM, 1, 1, bq, 1.f);
    TG_BIG(true, EPI_BIAS, memory, DM, 0L, 0L, Wk, DM, 0L, 0L, k, DM, 0L, 0L, ROWS, DM, DM, 1, 1, bk, 1.f);
    TG_BIG(true, EPI_BIAS, memory, DM, 0L, 0L, Wv, DM, 0L, 0L, v, DM, 0L, 0L, ROWS, DM, DM, 1, 1, bv, 1.f);

    // scores[b,h] = (1/8) * q_bh @ k_bh^T   (z = b*8+h)
    TG_BIG(true, EPI_NONE,
           q, DM, (long)LQ * DM, (long)HD,
           k, DM, (long)LK * DM, (long)HD,
           sc, LK, (long)NH * LQ * LK, (long)LQ * LK,
           LQ, LK, HD, NB * NH, NH, (const float*)nullptr, 0.125f);

    softmax_kernel<<<NB * NH * LQ, 256>>>(sc);

    // out_bh = attn_bh @ v_bh   (B not transposed, N=64)
    TG_N64(false, EPI_NONE,
           sc, LK, (long)NH * LQ * LK, (long)LQ * LK,
           v, DM, (long)LK * DM, (long)HD,
           ao, DM, (long)LQ * DM, (long)HD,
           LQ, HD, LK, NB * NH, NH, (const float*)nullptr, 1.f);

    // o-proj (reuse q buffer as output)
    TG_BIG(true, EPI_BIAS, ao, DM, 0L, 0L, Wo, DM, 0L, 0L, q, DM, 0L, 0L, ROWS, DM, DM, 1, 1, bo, 1.f);

    addln_kernel<<<ROWS, 256>>>(x, q, ln1g, ln1b, x1);

    // --- mamba ---
    TG_BIG(true, EPI_NONE, x1, DM, 0L, 0L, W_in, DM, 0L, 0L, xz, 2 * DI, 0L, 0L, ROWS, 2 * DI, DM, 1, 1, (const float*)nullptr, 1.f);

    conv_silu_kernel<<<(ROWS * DI) / 256, 256>>>(xz, conv_w, conv_b, u);

    TG_N64(true, EPI_NONE, u, DI, 0L, 0L, W_xproj, DI, 0L, 0L, xd, DTR + 2 * DS, 0L, 0L, ROWS, DTR + 2 * DS, DI, 1, 1, (const float*)nullptr, 1.f);

    // dt = softplus(dt_r @ W_dt^T + b_dt); dt_r is first 32 cols of xdbl (lda=64)
    TG_BIG(true, EPI_SOFTPLUS, xd, DTR + 2 * DS, 0L, 0L, W_dt, DTR, 0L, 0L, dtb, DI, 0L, 0L, ROWS, DI, DTR, 1, 1, b_dt, 1.f);

    scan_kernel<<<dim3(DI / 16, NB), 256>>>(xd, dtb, u, A_log, y);

    gate_kernel<<<(ROWS * DI) / 256, 256>>>(y, u, D_p, xz, ym);

    TG_BIG(true, EPI_NONE, ym, DI, 0L, 0L, W_out, DI, 0L, 0L, m, DM, 0L, 0L, ROWS, DM, DI, 1, 1, (const float*)nullptr, 1.f);

    addln_kernel<<<ROWS, 256>>>(x1, m, ln2g, ln2b, x2);

    // --- FFN ---
    TG_BIG(true, EPI_GELU, x2, DM, 0L, 0L, W1, DM, 0L, 0L, fh, 4 * DM, 0L, 0L, ROWS, 4 * DM, DM, 1, 1, b1, 1.f);
    TG_BIG(true, EPI_BIAS, fh, 4 * DM, 0L, 0L, W2, 4 * DM, 0L, 0L, ff, DM, 0L, 0L, ROWS, DM, 4 * DM, 1, 1, b2, 1.f);

    addln_kernel<<<ROWS, 256>>>(x2, ff, ln3g, ln3b, out);

#undef TG_BIG
#undef TG_N64
}

// round 8
// speedup vs baseline: 1.8050x; 1.2010x over previous
#include <cuda_runtime.h>
#include <mma.h>
#include <math.h>
#include <type_traits>

using namespace nvcuda;

// ---------------- constants ----------------
#define DM    512          // D_MODEL
#define LQ    1024         // SEQ
#define LK    1024         // MEMLEN
#define NB    4            // BATCH
#define NH    8            // heads
#define HD    64           // head dim
#define DI    1024         // D_INNER
#define DS    16           // D_STATE
#define DTR   32           // DT_RANK
#define ROWS  (NB*LQ)      // 4096

// ---------------- scratch (static device, no allocs) ----------------
__device__ float g_q   [ROWS*DM];
__device__ float g_k   [ROWS*DM];
__device__ float g_v   [ROWS*DM];
__device__ float g_sc  [(long)NB*NH*LQ*LK];   // 128 MB scores
__device__ float g_ao  [ROWS*DM];
__device__ float g_x1  [ROWS*DM];
__device__ float g_xz  [ROWS*2*DI];
__device__ float g_u   [ROWS*DI];
__device__ float g_xdbl[ROWS*(DTR+2*DS)];
__device__ float g_dt  [ROWS*DI];
__device__ float g_y   [ROWS*DI];
__device__ float g_ym  [ROWS*DI];
__device__ float g_m   [ROWS*DM];
__device__ float g_x2  [ROWS*DM];
__device__ float g_fh  [ROWS*4*DM];
__device__ float g_ff  [ROWS*DM];

enum { EPI_NONE = 0, EPI_BIAS = 1, EPI_SOFTPLUS = 2, EPI_GELU = 3 };

// ---------------- cp.async helpers ----------------
__device__ __forceinline__ void cpa16(float* dst, const float* src)
{
    unsigned d = (unsigned)__cvta_generic_to_shared(dst);
    asm volatile("cp.async.cg.shared.global [%0], [%1], 16;\n" :: "r"(d), "l"(src));
}
__device__ __forceinline__ void cpa_commit() { asm volatile("cp.async.commit_group;\n"); }
__device__ __forceinline__ void cpa_wait1()  { asm volatile("cp.async.wait_group 1;\n"); }
__device__ __forceinline__ void cpa_wait0()  { asm volatile("cp.async.wait_group 0;\n"); }

// ---------------- TF32 wmma GEMM, 2-stage cp.async pipeline ----------------
// C = alpha * A @ op(B) (+bias)(+act)
// A: M x K row-major (lda). TRANSB: B stored [N][K]; else [K][N].
// Batched via blockIdx.z: off = (z/zdiv)*s?o + (z%zdiv)*s?i
// 8 warps arranged WR x WC; warp tile (BM/WR) x (BN/WC); WTN must be 32.
// Requires: K % 16 == 0, all leading dims and row offsets 16B-aligned.

template <int BM, int BN, int WR, int WC, bool TRANSB, int EPI>
__global__ __launch_bounds__(256, 2) void tgemm(
    const float* __restrict__ A, int lda, long sAo, long sAi,
    const float* __restrict__ B, int ldb, long sBo, long sBi,
    float* __restrict__ C, int ldc, long sCo, long sCi,
    int K, int zdiv,
    const float* __restrict__ bias, float alpha)
{
    constexpr int BK   = 16;
    constexpr int WTM  = BM / WR;
    constexpr int WTN  = BN / WC;            // 32
    constexpr int FM   = WTM / 16;
    constexpr int FN   = WTN / 16;
    constexpr int LDAS = BK + 4;
    constexpr int LDBS = BK + 4;             // TRANSB: [BN][LDBS]
    constexpr int LDBN = BN + 4;             // !TRANSB: [BK][LDBN]
    constexpr int ASTG = BM * LDAS;
    constexpr int BSTG = TRANSB ? BN * LDBS : BK * LDBN;
    constexpr int ESLB = 16 * (WTN + 4);
    constexpr int PIPE = 2 * (ASTG + BSTG);
    constexpr int SMEMF = PIPE > (8 * ESLB) ? PIPE : (8 * ESLB);

    __shared__ float smem[SMEMF];
    float* As = smem;                        // 2 stages
    float* Bs = smem + 2 * ASTG;             // 2 stages

    int z = blockIdx.z;
    int zo = z / zdiv, zi = z % zdiv;
    A += zo * sAo + zi * sAi;
    B += zo * sBo + zi * sBi;
    C += zo * sCo + zi * sCi;

    const int tid  = threadIdx.x;
    const int wid  = tid >> 5;
    const int lane = tid & 31;
    const int warp_m = wid / WC;
    const int warp_n = wid % WC;
    const int row0 = blockIdx.y * BM;
    const int col0 = blockIdx.x * BN;

    using BLayout = typename std::conditional<TRANSB, wmma::col_major, wmma::row_major>::type;

    wmma::fragment<wmma::accumulator, 16, 16, 8, float> acc[FM][FN];
#pragma unroll
    for (int i = 0; i < FM; i++)
#pragma unroll
        for (int j = 0; j < FN; j++) wmma::fill_fragment(acc[i][j], 0.f);

    // ---- stage loaders ----
    auto load_stage = [&](int st, int k0) {
        constexpr int AITER = (BM * BK) / (256 * 4);
#pragma unroll
        for (int r = 0; r < AITER; r++) {
            int t = tid + 256 * r;
            int m  = t >> 2;
            int kc = (t & 3) * 4;
            cpa16(&As[st * ASTG + m * LDAS + kc], &A[(long)(row0 + m) * lda + k0 + kc]);
        }
        if (TRANSB) {
            constexpr int BITER = ((BN * BK) / (256 * 4)) ? ((BN * BK) / (256 * 4)) : 1;
#pragma unroll
            for (int r = 0; r < BITER; r++) {
                int t = tid + 256 * r;
                if (BITER * 256 > BN * 4 && t >= BN * 4) break;
                int n  = t >> 2;
                int kc = (t & 3) * 4;
                cpa16(&Bs[st * BSTG + n * LDBS + kc], &B[(long)(col0 + n) * ldb + k0 + kc]);
            }
        } else {
            constexpr int NV = BN / 4;
            constexpr int BITER = ((BK * NV) / 256) ? ((BK * NV) / 256) : 1;
#pragma unroll
            for (int r = 0; r < BITER; r++) {
                int t = tid + 256 * r;
                if (BITER * 256 > BK * NV && t >= BK * NV) break;
                int k  = t / NV;
                int nc = (t % NV) * 4;
                cpa16(&Bs[st * BSTG + k * LDBN + nc], &B[(long)(k0 + k) * ldb + col0 + nc]);
            }
        }
        cpa_commit();
    };

    // ---- prologue: prefetch stage 0 ----
    load_stage(0, 0);

    const int NIT = K / BK;
    for (int it = 0; it < NIT; it++) {
        int cur = it & 1;
        if (it + 1 < NIT) {
            load_stage(cur ^ 1, (it + 1) * BK);
            cpa_wait1();
        } else {
            cpa_wait0();
        }
        __syncthreads();

        const float* Ac = &As[cur * ASTG];
        const float* Bc = &Bs[cur * BSTG];
#pragma unroll
        for (int kk = 0; kk < BK; kk += 8) {
            wmma::fragment<wmma::matrix_a, 16, 16, 8, wmma::precision::tf32, wmma::row_major> af[FM];
#pragma unroll
            for (int i = 0; i < FM; i++) {
                wmma::load_matrix_sync(af[i], &Ac[(warp_m * WTM + i * 16) * LDAS + kk], LDAS);
#pragma unroll
                for (int t = 0; t < af[i].num_elements; t++)
                    af[i].x[t] = wmma::__float_to_tf32(af[i].x[t]);
            }
            wmma::fragment<wmma::matrix_b, 16, 16, 8, wmma::precision::tf32, BLayout> bf[FN];
#pragma unroll
            for (int j = 0; j < FN; j++) {
                const float* bptr = TRANSB ? &Bc[(warp_n * WTN + j * 16) * LDBS + kk]
                                           : &Bc[kk * LDBN + warp_n * WTN + j * 16];
                const int bld = TRANSB ? LDBS : LDBN;
                wmma::load_matrix_sync(bf[j], bptr, bld);
#pragma unroll
                for (int t = 0; t < bf[j].num_elements; t++)
                    bf[j].x[t] = wmma::__float_to_tf32(bf[j].x[t]);
            }
#pragma unroll
            for (int i = 0; i < FM; i++)
#pragma unroll
                for (int j = 0; j < FN; j++)
                    wmma::mma_sync(acc[i][j], af[i], bf[j], acc[i][j]);
        }
        __syncthreads();
    }

    if (EPI == EPI_NONE) {
        // uniform alpha: scale in-fragment (layout-independent), store direct to gmem
#pragma unroll
        for (int i = 0; i < FM; i++)
#pragma unroll
            for (int j = 0; j < FN; j++) {
                if (alpha != 1.f)
#pragma unroll
                    for (int t = 0; t < acc[i][j].num_elements; t++) acc[i][j].x[t] *= alpha;
                wmma::store_matrix_sync(
                    &C[(long)(row0 + warp_m * WTM + i * 16) * ldc + col0 + warp_n * WTN + j * 16],
                    acc[i][j], ldc, wmma::mem_row_major);
            }
    } else {
        // epilogue via per-warp smem slab (16 x WTN)
        float* slab = smem + wid * ESLB;
#pragma unroll
        for (int i = 0; i < FM; i++) {
#pragma unroll
            for (int j = 0; j < FN; j++)
                wmma::store_matrix_sync(slab + j * 16, acc[i][j], WTN + 4, wmma::mem_row_major);
            __syncwarp();
            int c = lane;                          // WTN == 32
            int n = col0 + warp_n * WTN + c;
            float bv = bias[n];
#pragma unroll
            for (int r = 0; r < 16; r++) {
                float val = slab[r * (WTN + 4) + c] * alpha + bv;
                if (EPI == EPI_SOFTPLUS) val = (val > 20.f) ? val : log1pf(expf(val));
                if (EPI == EPI_GELU)     val = 0.5f * val * (1.f + erff(val * 0.70710678118f));
                C[(long)(row0 + warp_m * WTM + i * 16 + r) * ldc + n] = val;
            }
            __syncwarp();
        }
    }
}

// ---------------- softmax over rows of length 1024 ----------------
__global__ __launch_bounds__(256) void softmax_kernel(float* __restrict__ S)
{
    long row = blockIdx.x;
    float* p = S + row * (long)LK;
    int tid = threadIdx.x;
    __shared__ float sred[8];

    float v[4];
    float mx = -1e30f;
#pragma unroll
    for (int i = 0; i < 4; i++) { v[i] = p[tid + 256 * i]; mx = fmaxf(mx, v[i]); }
#pragma unroll
    for (int o = 16; o; o >>= 1) mx = fmaxf(mx, __shfl_xor_sync(0xffffffffu, mx, o));
    if ((tid & 31) == 0) sred[tid >> 5] = mx;
    __syncthreads();
    if (tid < 8) {
        float t = sred[tid];
#pragma unroll
        for (int o = 4; o; o >>= 1) t = fmaxf(t, __shfl_xor_sync(0xffu, t, o));
        sred[tid] = t;
    }
    __syncthreads();
    mx = sred[0];
    __syncthreads();

    float sum = 0.f;
#pragma unroll
    for (int i = 0; i < 4; i++) { v[i] = __expf(v[i] - mx); sum += v[i]; }
#pragma unroll
    for (int o = 16; o; o >>= 1) sum += __shfl_xor_sync(0xffffffffu, sum, o);
    if ((tid & 31) == 0) sred[tid >> 5] = sum;
    __syncthreads();
    if (tid < 8) {
        float t = sred[tid];
#pragma unroll
        for (int o = 4; o; o >>= 1) t += __shfl_xor_sync(0xffu, t, o);
        sred[tid] = t;
    }
    __syncthreads();
    float inv = 1.f / sred[0];
#pragma unroll
    for (int i = 0; i < 4; i++) p[tid + 256 * i] = v[i] * inv;
}

// ---------------- add + layernorm over rows of 512 ----------------
__global__ __launch_bounds__(256) void addln_kernel(
    const float* __restrict__ X, const float* __restrict__ R,
    const float* __restrict__ gg, const float* __restrict__ bb,
    float* __restrict__ O)
{
    long row = blockIdx.x;
    const float* x = X + row * DM;
    const float* r = R + row * DM;
    int tid = threadIdx.x;
    __shared__ float s1[8], s2[8];

    float v0 = x[tid] + r[tid];
    float v1 = x[tid + 256] + r[tid + 256];
    float s = v0 + v1;
    float ss = v0 * v0 + v1 * v1;
#pragma unroll
    for (int o = 16; o; o >>= 1) {
        s += __shfl_xor_sync(0xffffffffu, s, o);
        ss += __shfl_xor_sync(0xffffffffu, ss, o);
    }
    if ((tid & 31) == 0) { s1[tid >> 5] = s; s2[tid >> 5] = ss; }
    __syncthreads();
    if (tid < 8) {
        float a = s1[tid], c = s2[tid];
#pragma unroll
        for (int o = 4; o; o >>= 1) {
            a += __shfl_xor_sync(0xffu, a, o);
            c += __shfl_xor_sync(0xffu, c, o);
        }
        s1[tid] = a; s2[tid] = c;
    }
    __syncthreads();
    float mu  = s1[0] * (1.f / DM);
    float var = s2[0] * (1.f / DM) - mu * mu;
    float inv = rsqrtf(var + 1e-5f);
    O[row * DM + tid]       = (v0 - mu) * inv * gg[tid]       + bb[tid];
    O[row * DM + tid + 256] = (v1 - mu) * inv * gg[tid + 256] + bb[tid + 256];
}

// ---------------- depthwise causal conv(4) + SiLU ----------------
__global__ __launch_bounds__(256) void conv_silu_kernel(
    const float* __restrict__ xz, const float* __restrict__ cw,
    const float* __restrict__ cb, float* __restrict__ u)
{
    long idx = (long)blockIdx.x * 256 + threadIdx.x;   // over ROWS*DI
    int d = (int)(idx % DI);
    long bt = idx / DI;
    int t = (int)(bt % LQ);
    long b = bt / LQ;
    const float* base = xz + (b * LQ) * (long)(2 * DI) + d;   // xm[b][.][d], stride 2*DI
    float acc = cb[d];
#pragma unroll
    for (int j = 0; j < 4; j++) {
        int tt = t + j - 3;
        if (tt >= 0) acc = fmaf(base[(long)tt * (2 * DI)], cw[d * 4 + j], acc);
    }
    u[idx] = acc / (1.f + expf(-acc));
}

// ---------------- selective scan ----------------
__global__ __launch_bounds__(256) void scan_kernel(
    const float* __restrict__ xdbl,   // (ROWS, 64): B at +32, C at +48
    const float* __restrict__ dt,     // (ROWS, DI)
    const float* __restrict__ u,      // (ROWS, DI)
    const float* __restrict__ A_log,  // (DI, DS)
    float* __restrict__ y)            // (ROWS, DI)
{
    int b = blockIdx.y;
    int ch0 = blockIdx.x * 16;
    int tid = threadIdx.x;
    int warp = tid >> 5, lane = tid & 31;
    int half = lane >> 4, s = lane & 15;
    int ch_local = warp * 2 + half;
    int ch = ch0 + ch_local;

    __shared__ float Bsh[64][DS];
    __shared__ float Csh[64][DS];
    __shared__ float dsh[16][65];
    __shared__ float ush[16][65];

    float Ac = -expf(A_log[ch * DS + s]);
    float h = 0.f;

    const float* xb  = xdbl + (long)b * LQ * 64;
    const float* dtb = dt   + (long)b * LQ * DI;
    const float* ub  = u    + (long)b * LQ * DI;
    float*       yb  = y    + (long)b * LQ * DI;

    for (int t0 = 0; t0 < LQ; t0 += 64) {
        __syncthreads();
#pragma unroll
        for (int r = 0; r < 4; r++) {
            int i = tid + 256 * r;            // 0..1023
            int tl = i >> 4, sl = i & 15;
            Bsh[tl][sl] = xb[(long)(t0 + tl) * 64 + DTR + sl];
            Csh[tl][sl] = xb[(long)(t0 + tl) * 64 + DTR + DS + sl];
            dsh[sl][tl] = dtb[(long)(t0 + tl) * DI + ch0 + sl];
            ush[sl][tl] = ub [(long)(t0 + tl) * DI + ch0 + sl];
        }
        __syncthreads();
#pragma unroll 4
        for (int tl = 0; tl < 64; tl++) {
            float dtv = dsh[ch_local][tl];
            float dA = __expf(dtv * Ac);
            h = fmaf(h, dA, dtv * Bsh[tl][s] * ush[ch_local][tl]);
            float p = h * Csh[tl][s];
            p += __shfl_xor_sync(0xffffffffu, p, 1);
            p += __shfl_xor_sync(0xffffffffu, p, 2);
            p += __shfl_xor_sync(0xffffffffu, p, 4);
            p += __shfl_xor_sync(0xffffffffu, p, 8);
            if (s == 0) yb[(long)(t0 + tl) * DI + ch] = p;
        }
    }
}

// ---------------- gate: ym = (y + u*Dp) * silu(z) ----------------
__global__ __launch_bounds__(256) void gate_kernel(
    const float* __restrict__ y, const float* __restrict__ u,
    const float* __restrict__ Dp, const float* __restrict__ xz,
    float* __restrict__ out)
{
    long idx = (long)blockIdx.x * 256 + threadIdx.x;   // over ROWS*DI
    int d = (int)(idx % DI);
    long bt = idx / DI;
    float z = xz[bt * (2 * DI) + DI + d];
    float val = (y[idx] + u[idx] * Dp[d]) * (z / (1.f + expf(-z)));
    out[idx] = val;
}

// ---------------- launcher ----------------
static float* sym(const void* s)
{
    void* p = nullptr;
    cudaGetSymbolAddress(&p, s);
    return (float*)p;
}

extern "C" void kernel_launch(void* const* d_in, const int* in_sizes, int n_in,
                              void* d_out, int out_size)
{
    const float* x      = (const float*)d_in[0];
    const float* memory = (const float*)d_in[1];
    const float* Wq = (const float*)d_in[2];  const float* bq = (const float*)d_in[3];
    const float* Wk = (const float*)d_in[4];  const float* bk = (const float*)d_in[5];
    const float* Wv = (const float*)d_in[6];  const float* bv = (const float*)d_in[7];
    const float* Wo = (const float*)d_in[8];  const float* bo = (const float*)d_in[9];
    const float* ln1g = (const float*)d_in[10]; const float* ln1b = (const float*)d_in[11];
    const float* ln2g = (const float*)d_in[12]; const float* ln2b = (const float*)d_in[13];
    const float* ln3g = (const float*)d_in[14]; const float* ln3b = (const float*)d_in[15];
    const float* W_in   = (const float*)d_in[16];
    const float* conv_w = (const float*)d_in[17];
    const float* conv_b = (const float*)d_in[18];
    const float* W_xproj = (const float*)d_in[19];
    const float* W_dt    = (const float*)d_in[20];
    const float* b_dt    = (const float*)d_in[21];
    const float* A_log   = (const float*)d_in[22];
    const float* D_p     = (const float*)d_in[23];
    const float* W_out   = (const float*)d_in[24];
    const float* W1 = (const float*)d_in[25]; const float* b1 = (const float*)d_in[26];
    const float* W2 = (const float*)d_in[27]; const float* b2 = (const float*)d_in[28];
    float* out = (float*)d_out;

    float* q    = sym(g_q);    float* k    = sym(g_k);    float* v   = sym(g_v);
    float* sc   = sym(g_sc);   float* ao   = sym(g_ao);   float* x1  = sym(g_x1);
    float* xz   = sym(g_xz);   float* u    = sym(g_u);    float* xd  = sym(g_xdbl);
    float* dtb  = sym(g_dt);   float* y    = sym(g_y);    float* ym  = sym(g_ym);
    float* m    = sym(g_m);    float* x2   = sym(g_x2);   float* fh  = sym(g_fh);
    float* ff   = sym(g_ff);

    // big-N config: 128x128 tile, warps 2x4 (warp tile 64x32)
#define TG_BIG(TB, EPI, A, lda, sAo, sAi, B, ldb, sBo, sBi, C, ldc, sCo, sCi, M, N, K, Z, zdiv, bias, alpha) \
    tgemm<128, 128, 2, 4, TB, EPI><<<dim3((N)/128, (M)/128, (Z)), 256>>>(                                    \
        A, lda, sAo, sAi, B, ldb, sBo, sBi, C, ldc, sCo, sCi, K, zdiv, bias, alpha)
    // N=64 config: 128x64 tile, warps 4x2 (warp tile 32x32)
#define TG_N64(TB, EPI, A, lda, sAo, sAi, B, ldb, sBo, sBi, C, ldc, sCo, sCi, M, N, K, Z, zdiv, bias, alpha) \
    tgemm<128, 64, 4, 2, TB, EPI><<<dim3((N)/64, (M)/128, (Z)), 256>>>(                                      \
        A, lda, sAo, sAi, B, ldb, sBo, sBi, C, ldc, sCo, sCi, K, zdiv, bias, alpha)

    // --- cross attention ---
    TG_BIG(true, EPI_BIAS, x,      DM, 0L, 0L, Wq, DM, 0L, 0L, q, DM, 0L, 0L, ROWS, DM, DM, 1, 1, bq, 1.f);
    TG_BIG(true, EPI_BIAS, memory, DM, 0L, 0L, Wk, DM, 0L, 0L, k, DM, 0L, 0L, ROWS, DM, DM, 1, 1, bk, 1.f);
    TG_BIG(true, EPI_BIAS, memory, DM, 0L, 0L, Wv, DM, 0L, 0L, v, DM, 0L, 0L, ROWS, DM, DM, 1, 1, bv, 1.f);

    // scores[b,h] = (1/8) * q_bh @ k_bh^T   (z = b*8+h)
    TG_BIG(true, EPI_NONE,
           q, DM, (long)LQ * DM, (long)HD,
           k, DM, (long)LK * DM, (long)HD,
           sc, LK, (long)NH * LQ * LK, (long)LQ * LK,
           LQ, LK, HD, NB * NH, NH, (const float*)nullptr, 0.125f);

    softmax_kernel<<<NB * NH * LQ, 256>>>(sc);

    // out_bh = attn_bh @ v_bh   (B not transposed, N=64)
    TG_N64(false, EPI_NONE,
           sc, LK, (long)NH * LQ * LK, (long)LQ * LK,
           v, DM, (long)LK * DM, (long)HD,
           ao, DM, (long)LQ * DM, (long)HD,
           LQ, HD, LK, NB * NH, NH, (const float*)nullptr, 1.f);

    // o-proj (reuse q buffer as output)
    TG_BIG(true, EPI_BIAS, ao, DM, 0L, 0L, Wo, DM, 0L, 0L, q, DM, 0L, 0L, ROWS, DM, DM, 1, 1, bo, 1.f);

    addln_kernel<<<ROWS, 256>>>(x, q, ln1g, ln1b, x1);

    // --- mamba ---
    TG_BIG(true, EPI_NONE, x1, DM, 0L, 0L, W_in, DM, 0L, 0L, xz, 2 * DI, 0L, 0L, ROWS, 2 * DI, DM, 1, 1, (const float*)nullptr, 1.f);

    conv_silu_kernel<<<(ROWS * DI) / 256, 256>>>(xz, conv_w, conv_b, u);

    TG_N64(true, EPI_NONE, u, DI, 0L, 0L, W_xproj, DI, 0L, 0L, xd, DTR + 2 * DS, 0L, 0L, ROWS, DTR + 2 * DS, DI, 1, 1, (const float*)nullptr, 1.f);

    // dt = softplus(dt_r @ W_dt^T + b_dt); dt_r is first 32 cols of xdbl (lda=64)
    TG_BIG(true, EPI_SOFTPLUS, xd, DTR + 2 * DS, 0L, 0L, W_dt, DTR, 0L, 0L, dtb, DI, 0L, 0L, ROWS, DI, DTR, 1, 1, b_dt, 1.f);

    scan_kernel<<<dim3(DI / 16, NB), 256>>>(xd, dtb, u, A_log, y);

    gate_kernel<<<(ROWS * DI) / 256, 256>>>(y, u, D_p, xz, ym);

    TG_BIG(true, EPI_NONE, ym, DI, 0L, 0L, W_out, DI, 0L, 0L, m, DM, 0L, 0L, ROWS, DM, DI, 1, 1, (const float*)nullptr, 1.f);

    addln_kernel<<<ROWS, 256>>>(x1, m, ln2g, ln2b, x2);

    // --- FFN ---
    TG_BIG(true, EPI_GELU, x2, DM, 0L, 0L, W1, DM, 0L, 0L, fh, 4 * DM, 0L, 0L, ROWS, 4 * DM, DM, 1, 1, b1, 1.f);
    TG_BIG(true, EPI_BIAS, fh, 4 * DM, 0L, 0L, W2, 4 * DM, 0L, 0L, ff, DM, 0L, 0L, ROWS, DM, 4 * DM, 1, 1, b2, 1.f);

    addln_kernel<<<ROWS, 256>>>(x2, ff, ln3g, ln3b, out);

#undef TG_BIG
#undef TG_N64
}